// round 7
// baseline (speedup 1.0000x reference)
#include <cuda_runtime.h>
#include <cuda_bf16.h>
#include <cstdint>

#define BB   8
#define NSQ  2048
#define DDIM 512
#define MTOT (BB * NSQ)

// ---------------- global scratch (bf16 hi/lo pairs + fp32 S) ---------------
__device__ __nv_bfloat16 g_xh[(size_t)MTOT * DDIM], g_xl[(size_t)MTOT * DDIM];
__device__ __nv_bfloat16 g_wh[3 * DDIM * DDIM],     g_wl[3 * DDIM * DDIM];
__device__ __nv_bfloat16 g_Qh[(size_t)MTOT * DDIM], g_Ql[(size_t)MTOT * DDIM];
__device__ __nv_bfloat16 g_Kh[(size_t)MTOT * DDIM], g_Kl[(size_t)MTOT * DDIM];
__device__ __nv_bfloat16 g_Vh[(size_t)MTOT * DDIM], g_Vl[(size_t)MTOT * DDIM];
__device__ float         g_S [(size_t)BB * NSQ * NSQ];
__device__ __nv_bfloat16 g_Ph[(size_t)BB * NSQ * NSQ], g_Pl[(size_t)BB * NSQ * NSQ];

// ---------------------------------------------------------------------------
// helpers
// ---------------------------------------------------------------------------
static __device__ __forceinline__ uint32_t smem_u32(const void* p) {
    uint32_t a;
    asm("{ .reg .u64 t; cvta.to.shared.u64 t, %1; cvt.u32.u64 %0, t; }"
        : "=r"(a) : "l"(p));
    return a;
}
static __device__ __forceinline__ void cpa16(uint32_t dst, const void* src) {
    asm volatile("cp.async.cg.shared.global [%0], [%1], 16;"
                 :: "r"(dst), "l"(src) : "memory");
}
#define CP_COMMIT() asm volatile("cp.async.commit_group;" ::: "memory")
#define CP_WAIT1()  asm volatile("cp.async.wait_group 1;" ::: "memory")
#define CP_WAIT0()  asm volatile("cp.async.wait_group 0;" ::: "memory")

// x,y fp32 -> packed bf16x2 hi (bit-truncate) / lo (rn residual); x->low half.
static __device__ __forceinline__ void split2(float x, float y,
                                              uint32_t& hi2, uint32_t& lo2) {
    uint32_t xb = __float_as_uint(x), yb = __float_as_uint(y);
    uint32_t h;
    asm("prmt.b32 %0, %1, %2, 0x7632;" : "=r"(h) : "r"(xb), "r"(yb));
    float xl = x - __uint_as_float(xb & 0xFFFF0000u);
    float yl = y - __uint_as_float(yb & 0xFFFF0000u);
    uint32_t l;
    asm("cvt.rn.bf16x2.f32 %0, %1, %2;" : "=r"(l) : "f"(yl), "f"(xl));
    hi2 = h; lo2 = l;
}

static __device__ __forceinline__ void mma16816(float c[4],
                                                const uint32_t a[4],
                                                uint32_t b0, uint32_t b1) {
    asm volatile(
        "mma.sync.aligned.m16n8k16.row.col.f32.bf16.bf16.f32 "
        "{%0,%1,%2,%3}, {%4,%5,%6,%7}, {%8,%9}, {%0,%1,%2,%3};"
        : "+f"(c[0]), "+f"(c[1]), "+f"(c[2]), "+f"(c[3])
        : "r"(a[0]), "r"(a[1]), "r"(a[2]), "r"(a[3]), "r"(b0), "r"(b1));
}

#define LDSM4(r0, r1, r2, r3, addr) \
    asm volatile("ldmatrix.sync.aligned.m8n8.x4.shared.b16 {%0,%1,%2,%3}, [%4];" \
                 : "=r"(r0), "=r"(r1), "=r"(r2), "=r"(r3) : "r"(addr))
#define LDSM4T(r0, r1, r2, r3, addr) \
    asm volatile("ldmatrix.sync.aligned.m8n8.x4.trans.shared.b16 {%0,%1,%2,%3}, [%4];" \
                 : "=r"(r0), "=r"(r1), "=r"(r2), "=r"(r3) : "r"(addr))

// ---------------------------------------------------------------------------
// fp32 -> bf16 hi/lo split (elementwise, float4 vectorized)
// ---------------------------------------------------------------------------
__global__ __launch_bounds__(256)
void split_kernel(const float* __restrict__ src,
                  __nv_bfloat16* __restrict__ h, __nv_bfloat16* __restrict__ l,
                  int n4)
{
    int i = blockIdx.x * 256 + threadIdx.x;
    if (i >= n4) return;
    float4 v = reinterpret_cast<const float4*>(src)[i];
    uint32_t h0, l0, h1, l1;
    split2(v.x, v.y, h0, l0);
    split2(v.z, v.w, h1, l1);
    reinterpret_cast<uint2*>(h)[i] = make_uint2(h0, h1);
    reinterpret_cast<uint2*>(l)[i] = make_uint2(l0, l1);
}

// ---------------------------------------------------------------------------
// 3xBF16 GEMM on pre-split operands.
//   BT=true : B is [N][K] K-major (proj, QK^T).  BT=false: B is [K][N] (PV).
//   OSPLIT  : write bf16 hi/lo output (+bias);  else fp32 output.
// 256 thr = 8 warps (2m x 4n), warp tile 64x32, BK=32, 3-stage cp.async.
// smem: A tiles 128 rows x 80B stride; B(!BT) tiles 32 rows x 272B stride.
// ---------------------------------------------------------------------------
template <bool BT, bool BIAS, bool OSPLIT>
__global__ __launch_bounds__(256, 1)
void mm_split(const __nv_bfloat16* __restrict__ Ah, const __nv_bfloat16* __restrict__ Al,
              int lda, long long bsA,
              const __nv_bfloat16* __restrict__ Bh, const __nv_bfloat16* __restrict__ Bl,
              int ldb, long long bsB,
              float* __restrict__ C,
              __nv_bfloat16* __restrict__ Oh, __nv_bfloat16* __restrict__ Ol,
              int ldc, long long bsC, int K, const float* __restrict__ bias)
{
    constexpr int A_T   = 10240;                 // bytes per A hi (or lo) tile
    constexpr int B_T   = BT ? 10240 : 8704;     // bytes per B hi (or lo) tile
    constexpr int BH_O  = 2 * A_T;               // B hi offset in stage
    constexpr int STAGE = 2 * A_T + 2 * B_T;

    extern __shared__ char smem[];
    const int tid  = threadIdx.x;
    const int lane = tid & 31, w = tid >> 5;
    const int wm = w & 1, wn = w >> 1;
    const int g = lane >> 2, t = lane & 3;
    const int quad = lane >> 3, qi = lane & 7;
    const int m0 = blockIdx.y * 128;
    const int n0 = blockIdx.x * 128;

    const long long aoff = blockIdx.z * bsA + (long long)m0 * lda;
    Ah += aoff; Al += aoff;
    const long long boff = blockIdx.z * bsB +
                           (BT ? (long long)n0 * ldb : (long long)n0);
    Bh += boff; Bl += boff;
    const long long coff = blockIdx.z * bsC + (long long)m0 * ldc + n0;
    if (OSPLIT) { Oh += coff; Ol += coff; }
    else        { C  += coff; }

    const uint32_t sbase = smem_u32(smem);
    const int KT = K / 32;

    float acc[4][4][4];
#pragma unroll
    for (int mi = 0; mi < 4; mi++)
#pragma unroll
        for (int ni = 0; ni < 4; ni++)
#pragma unroll
            for (int r = 0; r < 4; r++) acc[mi][ni][r] = 0.0f;

    // ---- async tile loader -----------------------------------------------
    auto load_tile = [&](int stage, int kt) {
        const int kofs = kt * 32;
        const uint32_t st = sbase + stage * STAGE;
#pragma unroll
        for (int j = 0; j < 8; j++) {
            const int idx = tid + j * 256;
            if (BT || idx < 1024) {
                const int arr = idx >> 9;           // 0:Ah 1:Al 2:Bh 3:Bl
                const int rem = idx & 511;
                const int row = rem >> 2, c4 = rem & 3;
                const __nv_bfloat16* gp =
                    (arr == 0) ? Ah : (arr == 1) ? Al : (arr == 2) ? Bh : Bl;
                const int ld = (arr < 2) ? lda : ldb;
                cpa16(st + arr * A_T + row * 80 + c4 * 16,
                      gp + (long long)row * ld + kofs + c4 * 8);
            } else {
                const int arr = (idx - 1024) >> 9;  // 0:Bh 1:Bl
                const int rem = (idx - 1024) & 511;
                const int row = rem >> 4, c = rem & 15;
                const __nv_bfloat16* gp = arr ? Bl : Bh;
                cpa16(st + BH_O + arr * B_T + row * 272 + c * 16,
                      gp + (long long)(kofs + row) * ldb + c * 8);
            }
        }
    };

    // ---- compute one ktile ------------------------------------------------
    auto compute = [&](int stage) {
        const uint32_t st = sbase + stage * STAGE;
#pragma unroll
        for (int ks = 0; ks < 2; ks++) {
            const int kb = ks * 16;
            uint32_t FAh[4][4], FAl[4][4];
#pragma unroll
            for (int mi = 0; mi < 4; mi++) {
                const uint32_t ro =
                    (uint32_t)(wm * 64 + mi * 16 + (quad & 1) * 8 + qi) * 80
                    + (uint32_t)(kb + (quad >> 1) * 8) * 2;
                LDSM4(FAh[mi][0], FAh[mi][1], FAh[mi][2], FAh[mi][3], st + ro);
                LDSM4(FAl[mi][0], FAl[mi][1], FAl[mi][2], FAl[mi][3],
                      st + A_T + ro);
            }
            uint32_t FBh[4][2], FBl[4][2];
#pragma unroll
            for (int nip = 0; nip < 2; nip++) {
                uint32_t r0, r1, r2, r3;
                if (BT) {
                    const uint32_t ro =
                        (uint32_t)(wn * 32 + nip * 16 + (quad & 1) * 8 + qi) * 80
                        + (uint32_t)(kb + (quad >> 1) * 8) * 2;
                    LDSM4(r0, r1, r2, r3, st + BH_O + ro);
                    FBh[2 * nip][0] = r0; FBh[2 * nip][1] = r2;
                    FBh[2 * nip + 1][0] = r1; FBh[2 * nip + 1][1] = r3;
                    LDSM4(r0, r1, r2, r3, st + BH_O + B_T + ro);
                    FBl[2 * nip][0] = r0; FBl[2 * nip][1] = r2;
                    FBl[2 * nip + 1][0] = r1; FBl[2 * nip + 1][1] = r3;
                } else {
                    const uint32_t ro =
                        (uint32_t)(kb + (quad >> 1) * 8 + qi) * 272
                        + (uint32_t)(wn * 32 + nip * 16 + (quad & 1) * 8) * 2;
                    LDSM4T(r0, r1, r2, r3, st + BH_O + ro);
                    FBh[2 * nip][0] = r0; FBh[2 * nip][1] = r2;
                    FBh[2 * nip + 1][0] = r1; FBh[2 * nip + 1][1] = r3;
                    LDSM4T(r0, r1, r2, r3, st + BH_O + B_T + ro);
                    FBl[2 * nip][0] = r0; FBl[2 * nip][1] = r2;
                    FBl[2 * nip + 1][0] = r1; FBl[2 * nip + 1][1] = r3;
                }
            }
#pragma unroll
            for (int mi = 0; mi < 4; mi++)
#pragma unroll
                for (int ni = 0; ni < 4; ni++) {
                    float* c = acc[mi][ni];
                    mma16816(c, FAh[mi], FBh[ni][0], FBh[ni][1]);
                    mma16816(c, FAh[mi], FBl[ni][0], FBl[ni][1]);
                    mma16816(c, FAl[mi], FBh[ni][0], FBh[ni][1]);
                }
        }
    };

    // ---- pipeline ---------------------------------------------------------
    load_tile(0, 0); CP_COMMIT();
    load_tile(1, 1); CP_COMMIT();

#pragma unroll 1
    for (int kt = 0; kt < KT; kt++) {
        if (kt < KT - 1) { CP_WAIT1(); } else { CP_WAIT0(); }
        __syncthreads();
        if (kt + 2 < KT) { load_tile((kt + 2) % 3, kt + 2); CP_COMMIT(); }
        compute(kt % 3);
    }

    // ---- epilogue ---------------------------------------------------------
#pragma unroll
    for (int mi = 0; mi < 4; mi++) {
#pragma unroll
        for (int ni = 0; ni < 4; ni++) {
            const int col = wn * 32 + ni * 8 + 2 * t;
            float bx = 0.0f, by = 0.0f;
            if (BIAS) {
                const float2 bv = *reinterpret_cast<const float2*>(bias + n0 + col);
                bx = bv.x; by = bv.y;
            }
            const int r0 = wm * 64 + mi * 16 + g;
            const float v0 = acc[mi][ni][0] + bx, v1 = acc[mi][ni][1] + by;
            const float v2 = acc[mi][ni][2] + bx, v3 = acc[mi][ni][3] + by;
            if (OSPLIT) {
                uint32_t h2, l2;
                split2(v0, v1, h2, l2);
                *reinterpret_cast<uint32_t*>(Oh + (long long)r0 * ldc + col) = h2;
                *reinterpret_cast<uint32_t*>(Ol + (long long)r0 * ldc + col) = l2;
                split2(v2, v3, h2, l2);
                *reinterpret_cast<uint32_t*>(Oh + (long long)(r0 + 8) * ldc + col) = h2;
                *reinterpret_cast<uint32_t*>(Ol + (long long)(r0 + 8) * ldc + col) = l2;
            } else {
                *reinterpret_cast<float2*>(C + (long long)r0 * ldc + col) =
                    make_float2(v0, v1);
                *reinterpret_cast<float2*>(C + (long long)(r0 + 8) * ldc + col) =
                    make_float2(v2, v3);
            }
        }
    }
}

// ---------------------------------------------------------------------------
// Row softmax (len 2048) reading fp32 S, writing bf16 hi/lo P.
// Max-subtraction mandatory (unscaled logits ~±90).
// ---------------------------------------------------------------------------
__global__ __launch_bounds__(256)
void softmax_split(const float* __restrict__ S,
                   __nv_bfloat16* __restrict__ Ph, __nv_bfloat16* __restrict__ Pl)
{
    const long long row = blockIdx.x;
    const float* p = S + row * (long long)NSQ;
    const int tid = threadIdx.x;

    float v[8];
    {
        float4 a = reinterpret_cast<const float4*>(p)[tid * 2];
        float4 b = reinterpret_cast<const float4*>(p)[tid * 2 + 1];
        v[0] = a.x; v[1] = a.y; v[2] = a.z; v[3] = a.w;
        v[4] = b.x; v[5] = b.y; v[6] = b.z; v[7] = b.w;
    }
    float m = v[0];
#pragma unroll
    for (int i = 1; i < 8; i++) m = fmaxf(m, v[i]);

    __shared__ float red[256];
    red[tid] = m;
    __syncthreads();
#pragma unroll
    for (int s = 128; s > 0; s >>= 1) {
        if (tid < s) red[tid] = fmaxf(red[tid], red[tid + s]);
        __syncthreads();
    }
    m = red[0];
    __syncthreads();

    float sum = 0.0f;
#pragma unroll
    for (int i = 0; i < 8; i++) {
        v[i] = __expf(v[i] - m);
        sum += v[i];
    }
    red[tid] = sum;
    __syncthreads();
#pragma unroll
    for (int s = 128; s > 0; s >>= 1) {
        if (tid < s) red[tid] += red[tid + s];
        __syncthreads();
    }
    const float inv = 1.0f / red[0];

    uint32_t h[4], l[4];
#pragma unroll
    for (int i = 0; i < 4; i++)
        split2(v[2 * i] * inv, v[2 * i + 1] * inv, h[i], l[i]);
    const long long o = row * (long long)NSQ + tid * 8;
    *reinterpret_cast<uint4*>(Ph + o) = make_uint4(h[0], h[1], h[2], h[3]);
    *reinterpret_cast<uint4*>(Pl + o) = make_uint4(l[0], l[1], l[2], l[3]);
}

// ---------------------------------------------------------------------------
// Launch
// ---------------------------------------------------------------------------
extern "C" void kernel_launch(void* const* d_in, const int* in_sizes, int n_in,
                              void* d_out, int out_size)
{
    const float* x  = (const float*)d_in[0];
    const float* Wq = (const float*)d_in[1];
    const float* bq = (const float*)d_in[2];
    const float* Wk = (const float*)d_in[3];
    const float* bk = (const float*)d_in[4];
    const float* Wv = (const float*)d_in[5];
    const float* bv = (const float*)d_in[6];
    float* out = (float*)d_out;

    __nv_bfloat16 *xh, *xl, *wh, *wl, *Qh, *Ql, *Kh, *Kl, *Vh, *Vl, *Ph, *Pl;
    float* S;
    cudaGetSymbolAddress((void**)&xh, g_xh); cudaGetSymbolAddress((void**)&xl, g_xl);
    cudaGetSymbolAddress((void**)&wh, g_wh); cudaGetSymbolAddress((void**)&wl, g_wl);
    cudaGetSymbolAddress((void**)&Qh, g_Qh); cudaGetSymbolAddress((void**)&Ql, g_Ql);
    cudaGetSymbolAddress((void**)&Kh, g_Kh); cudaGetSymbolAddress((void**)&Kl, g_Kl);
    cudaGetSymbolAddress((void**)&Vh, g_Vh); cudaGetSymbolAddress((void**)&Vl, g_Vl);
    cudaGetSymbolAddress((void**)&Ph, g_Ph); cudaGetSymbolAddress((void**)&Pl, g_Pl);
    cudaGetSymbolAddress((void**)&S,  g_S);

    const int SMEM_BT = 3 * (2 * 10240 + 2 * 10240);  // 122880
    const int SMEM_BN = 3 * (2 * 10240 + 2 * 8704);   // 113664
    cudaFuncSetAttribute(mm_split<true, true, true>,
                         cudaFuncAttributeMaxDynamicSharedMemorySize, SMEM_BT);
    cudaFuncSetAttribute(mm_split<true, false, false>,
                         cudaFuncAttributeMaxDynamicSharedMemorySize, SMEM_BT);
    cudaFuncSetAttribute(mm_split<false, false, false>,
                         cudaFuncAttributeMaxDynamicSharedMemorySize, SMEM_BN);

    // 0) pre-split inputs to bf16 hi/lo
    {
        const int nx4 = MTOT * DDIM / 4;      // 2,097,152
        split_kernel<<<(nx4 + 255) / 256, 256>>>(x, xh, xl, nx4);
        const int nw4 = DDIM * DDIM / 4;      // 65,536
        split_kernel<<<(nw4 + 255) / 256, 256>>>(Wq, wh, wl, nw4);
        split_kernel<<<(nw4 + 255) / 256, 256>>>(Wk, wh + DDIM * DDIM,
                                                 wl + DDIM * DDIM, nw4);
        split_kernel<<<(nw4 + 255) / 256, 256>>>(Wv, wh + 2 * DDIM * DDIM,
                                                 wl + 2 * DDIM * DDIM, nw4);
    }
    // 1) projections -> split bf16 Q/K/V
    {
        dim3 grid(DDIM / 128, MTOT / 128, 1);
        mm_split<true, true, true><<<grid, 256, SMEM_BT>>>(
            xh, xl, DDIM, 0, wh, wl, DDIM, 0,
            nullptr, Qh, Ql, DDIM, 0, DDIM, bq);
        mm_split<true, true, true><<<grid, 256, SMEM_BT>>>(
            xh, xl, DDIM, 0, wh + DDIM * DDIM, wl + DDIM * DDIM, DDIM, 0,
            nullptr, Kh, Kl, DDIM, 0, DDIM, bk);
        mm_split<true, true, true><<<grid, 256, SMEM_BT>>>(
            xh, xl, DDIM, 0, wh + 2 * DDIM * DDIM, wl + 2 * DDIM * DDIM, DDIM, 0,
            nullptr, Vh, Vl, DDIM, 0, DDIM, bv);
    }
    // 2) scores: S_b = Q_b @ K_b^T (fp32 out)
    {
        dim3 grid(NSQ / 128, NSQ / 128, BB);
        mm_split<true, false, false><<<grid, 256, SMEM_BT>>>(
            Qh, Ql, DDIM, (long long)NSQ * DDIM,
            Kh, Kl, DDIM, (long long)NSQ * DDIM,
            S, nullptr, nullptr, NSQ, (long long)NSQ * NSQ, DDIM, nullptr);
    }
    // 3) softmax -> split bf16 P
    softmax_split<<<BB * NSQ, 256>>>(S, Ph, Pl);
    // 4) output: O_b = P_b @ V_b (fp32 out)
    {
        dim3 grid(DDIM / 128, NSQ / 128, BB);
        mm_split<false, false, false><<<grid, 256, SMEM_BN>>>(
            Ph, Pl, NSQ, (long long)NSQ * NSQ,
            Vh, Vl, DDIM, (long long)NSQ * DDIM,
            out, nullptr, nullptr, DDIM, (long long)NSQ * DDIM, NSQ, nullptr);
    }
}

// round 12
// speedup vs baseline: 1.3120x; 1.3120x over previous
#include <cuda_runtime.h>
#include <cuda_bf16.h>
#include <cuda_fp16.h>
#include <cstdint>

#define BB   8
#define NSQ  2048
#define DDIM 512
#define MTOT (BB * NSQ)

// ---------------- global scratch ----------------
__device__ __nv_bfloat16 g_xh[(size_t)MTOT * DDIM], g_xl[(size_t)MTOT * DDIM];
__device__ __nv_bfloat16 g_wh[3 * DDIM * DDIM],     g_wl[3 * DDIM * DDIM];
__device__ __nv_bfloat16 g_Qh[(size_t)MTOT * DDIM], g_Ql[(size_t)MTOT * DDIM];
__device__ __nv_bfloat16 g_Kh[(size_t)MTOT * DDIM], g_Kl[(size_t)MTOT * DDIM];
__device__ __half        g_Vf[(size_t)MTOT * DDIM];
__device__ float         g_S [(size_t)BB * NSQ * NSQ];
__device__ __half        g_Pf[(size_t)BB * NSQ * NSQ];

// ---------------------------------------------------------------------------
// helpers
// ---------------------------------------------------------------------------
static __device__ __forceinline__ uint32_t smem_u32(const void* p) {
    uint32_t a;
    asm("{ .reg .u64 t; cvta.to.shared.u64 t, %1; cvt.u32.u64 %0, t; }"
        : "=r"(a) : "l"(p));
    return a;
}
static __device__ __forceinline__ void cpa16(uint32_t dst, const void* src) {
    asm volatile("cp.async.cg.shared.global [%0], [%1], 16;"
                 :: "r"(dst), "l"(src) : "memory");
}
#define CP_COMMIT() asm volatile("cp.async.commit_group;" ::: "memory")
#define CP_WAIT1()  asm volatile("cp.async.wait_group 1;" ::: "memory")
#define CP_WAIT0()  asm volatile("cp.async.wait_group 0;" ::: "memory")

// fp32 x,y -> packed bf16x2 hi (bit-truncate) / lo (rn residual); x low half.
static __device__ __forceinline__ void split2(float x, float y,
                                              uint32_t& hi2, uint32_t& lo2) {
    uint32_t xb = __float_as_uint(x), yb = __float_as_uint(y);
    uint32_t h;
    asm("prmt.b32 %0, %1, %2, 0x7632;" : "=r"(h) : "r"(xb), "r"(yb));
    float xl = x - __uint_as_float(xb & 0xFFFF0000u);
    float yl = y - __uint_as_float(yb & 0xFFFF0000u);
    uint32_t l;
    asm("cvt.rn.bf16x2.f32 %0, %1, %2;" : "=r"(l) : "f"(yl), "f"(xl));
    hi2 = h; lo2 = l;
}
static __device__ __forceinline__ uint32_t packh2(float x, float y) {
    uint32_t r;
    asm("cvt.rn.f16x2.f32 %0, %1, %2;" : "=r"(r) : "f"(y), "f"(x));
    return r;
}

static __device__ __forceinline__ void mma_bf(float c[4], const uint32_t a[4],
                                              uint32_t b0, uint32_t b1) {
    asm volatile(
        "mma.sync.aligned.m16n8k16.row.col.f32.bf16.bf16.f32 "
        "{%0,%1,%2,%3}, {%4,%5,%6,%7}, {%8,%9}, {%0,%1,%2,%3};"
        : "+f"(c[0]), "+f"(c[1]), "+f"(c[2]), "+f"(c[3])
        : "r"(a[0]), "r"(a[1]), "r"(a[2]), "r"(a[3]), "r"(b0), "r"(b1));
}
static __device__ __forceinline__ void mma_fp(float c[4], const uint32_t a[4],
                                              uint32_t b0, uint32_t b1) {
    asm volatile(
        "mma.sync.aligned.m16n8k16.row.col.f32.f16.f16.f32 "
        "{%0,%1,%2,%3}, {%4,%5,%6,%7}, {%8,%9}, {%0,%1,%2,%3};"
        : "+f"(c[0]), "+f"(c[1]), "+f"(c[2]), "+f"(c[3])
        : "r"(a[0]), "r"(a[1]), "r"(a[2]), "r"(a[3]), "r"(b0), "r"(b1));
}

#define LDSM4(r0, r1, r2, r3, addr) \
    asm volatile("ldmatrix.sync.aligned.m8n8.x4.shared.b16 {%0,%1,%2,%3}, [%4];" \
                 : "=r"(r0), "=r"(r1), "=r"(r2), "=r"(r3) : "r"(addr))
#define LDSM4T(r0, r1, r2, r3, addr) \
    asm volatile("ldmatrix.sync.aligned.m8n8.x4.trans.shared.b16 {%0,%1,%2,%3}, [%4];" \
                 : "=r"(r0), "=r"(r1), "=r"(r2), "=r"(r3) : "r"(addr))

// ---------------------------------------------------------------------------
// fp32 -> bf16 hi/lo split (elementwise)
// ---------------------------------------------------------------------------
__global__ __launch_bounds__(256)
void split_kernel(const float* __restrict__ src,
                  __nv_bfloat16* __restrict__ h, __nv_bfloat16* __restrict__ l,
                  int n4)
{
    int i = blockIdx.x * 256 + threadIdx.x;
    if (i >= n4) return;
    float4 v = reinterpret_cast<const float4*>(src)[i];
    uint32_t h0, l0, h1, l1;
    split2(v.x, v.y, h0, l0);
    split2(v.z, v.w, h1, l1);
    reinterpret_cast<uint2*>(h)[i] = make_uint2(h0, h1);
    reinterpret_cast<uint2*>(l)[i] = make_uint2(l0, l1);
}

// ---------------------------------------------------------------------------
// 3xBF16 GEMM on pre-split operands, B is [N][K] K-major.
// OUT: 0 = fp32 C, 1 = bf16 hi/lo, 2 = fp16.   BIAS adds bias[n].
// 256 thr = 8 warps (2m x 4n), warp tile 64x32, BK=32, 3-stage cp.async.
// MMA order: split-term outermost (no same-accumulator back-to-back RAW).
// ---------------------------------------------------------------------------
template <int OUT, bool BIAS>
__global__ __launch_bounds__(256, 1)
void mm3(const __nv_bfloat16* __restrict__ Ah, const __nv_bfloat16* __restrict__ Al,
         int lda, long long bsA,
         const __nv_bfloat16* __restrict__ Bh, const __nv_bfloat16* __restrict__ Bl,
         int ldb, long long bsB,
         float* __restrict__ C, __nv_bfloat16* __restrict__ Oh,
         __nv_bfloat16* __restrict__ Ol, __half* __restrict__ F,
         int ldc, long long bsC, int K, const float* __restrict__ bias)
{
    constexpr int A_T   = 10240;        // bytes per (hi or lo) tile: 128 x 80B
    constexpr int STAGE = 4 * A_T;

    extern __shared__ char smem[];
    const int tid  = threadIdx.x;
    const int lane = tid & 31, w = tid >> 5;
    const int wm = w & 1, wn = w >> 1;
    const int g = lane >> 2, t = lane & 3;
    const int quad = lane >> 3, qi = lane & 7;
    const int m0 = blockIdx.y * 128;
    const int n0 = blockIdx.x * 128;

    const long long aoff = blockIdx.z * bsA + (long long)m0 * lda;
    Ah += aoff; Al += aoff;
    const long long boff = blockIdx.z * bsB + (long long)n0 * ldb;
    Bh += boff; Bl += boff;
    const long long coff = blockIdx.z * bsC + (long long)m0 * ldc + n0;

    const uint32_t sbase = smem_u32(smem);
    const int KT = K / 32;

    float acc[4][4][4];
#pragma unroll
    for (int mi = 0; mi < 4; mi++)
#pragma unroll
        for (int ni = 0; ni < 4; ni++)
#pragma unroll
            for (int r = 0; r < 4; r++) acc[mi][ni][r] = 0.0f;

    auto load_tile = [&](int stage, int kt) {
        const int kofs = kt * 32;
        const uint32_t st = sbase + stage * STAGE;
#pragma unroll
        for (int j = 0; j < 8; j++) {
            const int idx = tid + j * 256;
            const int arr = idx >> 9;            // 0:Ah 1:Al 2:Bh 3:Bl
            const int rem = idx & 511;
            const int row = rem >> 2, c4 = rem & 3;
            const __nv_bfloat16* gp =
                (arr == 0) ? Ah : (arr == 1) ? Al : (arr == 2) ? Bh : Bl;
            const int ld = (arr < 2) ? lda : ldb;
            cpa16(st + arr * A_T + row * 80 + c4 * 16,
                  gp + (long long)row * ld + kofs + c4 * 8);
        }
    };

    auto compute = [&](int stage) {
        const uint32_t st = sbase + stage * STAGE;
#pragma unroll
        for (int ks = 0; ks < 2; ks++) {
            const int kb = ks * 16;
            uint32_t FAh[4][4], FAl[4][4], FBh[4][2], FBl[4][2];
#pragma unroll
            for (int mi = 0; mi < 4; mi++) {
                const uint32_t ro =
                    (uint32_t)(wm * 64 + mi * 16 + (quad & 1) * 8 + qi) * 80
                    + (uint32_t)(kb + (quad >> 1) * 8) * 2;
                LDSM4(FAh[mi][0], FAh[mi][1], FAh[mi][2], FAh[mi][3], st + ro);
                LDSM4(FAl[mi][0], FAl[mi][1], FAl[mi][2], FAl[mi][3],
                      st + A_T + ro);
            }
#pragma unroll
            for (int nip = 0; nip < 2; nip++) {
                const uint32_t ro =
                    (uint32_t)(wn * 32 + nip * 16 + (quad & 1) * 8 + qi) * 80
                    + (uint32_t)(kb + (quad >> 1) * 8) * 2;
                uint32_t r0, r1, r2, r3;
                LDSM4(r0, r1, r2, r3, st + 2 * A_T + ro);
                FBh[2 * nip][0] = r0; FBh[2 * nip][1] = r2;
                FBh[2 * nip + 1][0] = r1; FBh[2 * nip + 1][1] = r3;
                LDSM4(r0, r1, r2, r3, st + 3 * A_T + ro);
                FBl[2 * nip][0] = r0; FBl[2 * nip][1] = r2;
                FBl[2 * nip + 1][0] = r1; FBl[2 * nip + 1][1] = r3;
            }
            // term-outermost: same-acc MMAs are 16 apart
#pragma unroll
            for (int mi = 0; mi < 4; mi++)
#pragma unroll
                for (int ni = 0; ni < 4; ni++)
                    mma_bf(acc[mi][ni], FAh[mi], FBh[ni][0], FBh[ni][1]);
#pragma unroll
            for (int mi = 0; mi < 4; mi++)
#pragma unroll
                for (int ni = 0; ni < 4; ni++)
                    mma_bf(acc[mi][ni], FAh[mi], FBl[ni][0], FBl[ni][1]);
#pragma unroll
            for (int mi = 0; mi < 4; mi++)
#pragma unroll
                for (int ni = 0; ni < 4; ni++)
                    mma_bf(acc[mi][ni], FAl[mi], FBh[ni][0], FBh[ni][1]);
        }
    };

    load_tile(0, 0); CP_COMMIT();
    load_tile(1, 1); CP_COMMIT();

#pragma unroll 1
    for (int kt = 0; kt < KT; kt++) {
        if (kt < KT - 1) { CP_WAIT1(); } else { CP_WAIT0(); }
        __syncthreads();
        if (kt + 2 < KT) { load_tile((kt + 2) % 3, kt + 2); CP_COMMIT(); }
        compute(kt % 3);
    }

#pragma unroll
    for (int mi = 0; mi < 4; mi++) {
#pragma unroll
        for (int ni = 0; ni < 4; ni++) {
            const int col = wn * 32 + ni * 8 + 2 * t;
            float bx = 0.0f, by = 0.0f;
            if (BIAS) {
                const float2 bv = *reinterpret_cast<const float2*>(bias + n0 + col);
                bx = bv.x; by = bv.y;
            }
            const int r0 = wm * 64 + mi * 16 + g;
            const float v0 = acc[mi][ni][0] + bx, v1 = acc[mi][ni][1] + by;
            const float v2 = acc[mi][ni][2] + bx, v3 = acc[mi][ni][3] + by;
            if (OUT == 1) {
                uint32_t h2, l2;
                split2(v0, v1, h2, l2);
                *reinterpret_cast<uint32_t*>(Oh + coff + (long long)r0 * ldc + col) = h2;
                *reinterpret_cast<uint32_t*>(Ol + coff + (long long)r0 * ldc + col) = l2;
                split2(v2, v3, h2, l2);
                *reinterpret_cast<uint32_t*>(Oh + coff + (long long)(r0 + 8) * ldc + col) = h2;
                *reinterpret_cast<uint32_t*>(Ol + coff + (long long)(r0 + 8) * ldc + col) = l2;
            } else if (OUT == 2) {
                *reinterpret_cast<uint32_t*>(F + coff + (long long)r0 * ldc + col) =
                    packh2(v0, v1);
                *reinterpret_cast<uint32_t*>(F + coff + (long long)(r0 + 8) * ldc + col) =
                    packh2(v2, v3);
            } else {
                *reinterpret_cast<float2*>(C + coff + (long long)r0 * ldc + col) =
                    make_float2(v0, v1);
                *reinterpret_cast<float2*>(C + coff + (long long)(r0 + 8) * ldc + col) =
                    make_float2(v2, v3);
            }
        }
    }
}

// ---------------------------------------------------------------------------
// Plain fp16 GEMM (single term): C = A[M,K](fp16, K-major) @ B[K,N](fp16,
// N-major), fp32 out.  BK=64, warp tile 64x32, 3-stage cp.async.
// A smem stride 144B (conflict-free LDSM), B stride 272B (LDSM4T).
// ---------------------------------------------------------------------------
__global__ __launch_bounds__(256, 1)
void mm_f16(const __half* __restrict__ A, int lda, long long bsA,
            const __half* __restrict__ B, int ldb, long long bsB,
            float* __restrict__ C, int ldc, long long bsC, int K)
{
    constexpr int A_T   = 128 * 144;    // 18432
    constexpr int B_T   = 64 * 272;     // 17408
    constexpr int STAGE = A_T + B_T;    // 35840

    extern __shared__ char smem[];
    const int tid  = threadIdx.x;
    const int lane = tid & 31, w = tid >> 5;
    const int wm = w & 1, wn = w >> 1;
    const int g = lane >> 2, t = lane & 3;
    const int quad = lane >> 3, qi = lane & 7;
    const int m0 = blockIdx.y * 128;
    const int n0 = blockIdx.x * 128;

    A += blockIdx.z * bsA + (long long)m0 * lda;
    B += blockIdx.z * bsB + n0;
    C += blockIdx.z * bsC + (long long)m0 * ldc + n0;

    const uint32_t sbase = smem_u32(smem);
    const int KT = K / 64;

    float acc[4][4][4];
#pragma unroll
    for (int mi = 0; mi < 4; mi++)
#pragma unroll
        for (int ni = 0; ni < 4; ni++)
#pragma unroll
            for (int r = 0; r < 4; r++) acc[mi][ni][r] = 0.0f;

    auto load_tile = [&](int stage, int kt) {
        const int kofs = kt * 64;
        const uint32_t st = sbase + stage * STAGE;
#pragma unroll
        for (int j = 0; j < 4; j++) {          // A: 1024 chunks
            const int idx = tid + j * 256;
            const int row = idx >> 3, c4 = idx & 7;
            cpa16(st + row * 144 + c4 * 16,
                  A + (long long)row * lda + kofs + c4 * 8);
        }
#pragma unroll
        for (int j = 0; j < 4; j++) {          // B: 1024 chunks
            const int idx = tid + j * 256;
            const int row = idx >> 4, c = idx & 15;
            cpa16(st + A_T + row * 272 + c * 16,
                  B + (long long)(kofs + row) * ldb + c * 8);
        }
    };

    auto compute = [&](int stage) {
        const uint32_t st = sbase + stage * STAGE;
#pragma unroll
        for (int ks = 0; ks < 4; ks++) {
            const int kb = ks * 16;
            uint32_t FA[4][4], FB[4][2];
#pragma unroll
            for (int mi = 0; mi < 4; mi++) {
                const uint32_t ro =
                    (uint32_t)(wm * 64 + mi * 16 + (quad & 1) * 8 + qi) * 144
                    + (uint32_t)(kb + (quad >> 1) * 8) * 2;
                LDSM4(FA[mi][0], FA[mi][1], FA[mi][2], FA[mi][3], st + ro);
            }
#pragma unroll
            for (int nip = 0; nip < 2; nip++) {
                const uint32_t ro =
                    (uint32_t)(kb + (quad >> 1) * 8 + qi) * 272
                    + (uint32_t)(wn * 32 + nip * 16 + (quad & 1) * 8) * 2;
                uint32_t r0, r1, r2, r3;
                LDSM4T(r0, r1, r2, r3, st + A_T + ro);
                FB[2 * nip][0] = r0; FB[2 * nip][1] = r2;
                FB[2 * nip + 1][0] = r1; FB[2 * nip + 1][1] = r3;
            }
#pragma unroll
            for (int mi = 0; mi < 4; mi++)
#pragma unroll
                for (int ni = 0; ni < 4; ni++)
                    mma_fp(acc[mi][ni], FA[mi], FB[ni][0], FB[ni][1]);
        }
    };

    load_tile(0, 0); CP_COMMIT();
    load_tile(1, 1); CP_COMMIT();

#pragma unroll 1
    for (int kt = 0; kt < KT; kt++) {
        if (kt < KT - 1) { CP_WAIT1(); } else { CP_WAIT0(); }
        __syncthreads();
        if (kt + 2 < KT) { load_tile((kt + 2) % 3, kt + 2); CP_COMMIT(); }
        compute(kt % 3);
    }

#pragma unroll
    for (int mi = 0; mi < 4; mi++) {
#pragma unroll
        for (int ni = 0; ni < 4; ni++) {
            const int col = wn * 32 + ni * 8 + 2 * t;
            const int r0 = wm * 64 + mi * 16 + g;
            *reinterpret_cast<float2*>(C + (long long)r0 * ldc + col) =
                make_float2(acc[mi][ni][0], acc[mi][ni][1]);
            *reinterpret_cast<float2*>(C + (long long)(r0 + 8) * ldc + col) =
                make_float2(acc[mi][ni][2], acc[mi][ni][3]);
        }
    }
}

// ---------------------------------------------------------------------------
// Row softmax (len 2048): fp32 S in, fp16 P out. Max-subtraction mandatory.
// ---------------------------------------------------------------------------
__global__ __launch_bounds__(256)
void softmax_f16(const float* __restrict__ S, __half* __restrict__ P)
{
    const long long row = blockIdx.x;
    const float* p = S + row * (long long)NSQ;
    const int tid = threadIdx.x;

    float v[8];
    {
        float4 a = reinterpret_cast<const float4*>(p)[tid * 2];
        float4 b = reinterpret_cast<const float4*>(p)[tid * 2 + 1];
        v[0] = a.x; v[1] = a.y; v[2] = a.z; v[3] = a.w;
        v[4] = b.x; v[5] = b.y; v[6] = b.z; v[7] = b.w;
    }
    float m = v[0];
#pragma unroll
    for (int i = 1; i < 8; i++) m = fmaxf(m, v[i]);

    __shared__ float red[256];
    red[tid] = m;
    __syncthreads();
#pragma unroll
    for (int s = 128; s > 0; s >>= 1) {
        if (tid < s) red[tid] = fmaxf(red[tid], red[tid + s]);
        __syncthreads();
    }
    m = red[0];
    __syncthreads();

    float sum = 0.0f;
#pragma unroll
    for (int i = 0; i < 8; i++) {
        v[i] = __expf(v[i] - m);
        sum += v[i];
    }
    red[tid] = sum;
    __syncthreads();
#pragma unroll
    for (int s = 128; s > 0; s >>= 1) {
        if (tid < s) red[tid] += red[tid + s];
        __syncthreads();
    }
    const float inv = 1.0f / red[0];

    uint32_t h[4];
#pragma unroll
    for (int i = 0; i < 4; i++)
        h[i] = packh2(v[2 * i] * inv, v[2 * i + 1] * inv);
    *reinterpret_cast<uint4*>(P + row * (long long)NSQ + tid * 8) =
        make_uint4(h[0], h[1], h[2], h[3]);
}

// ---------------------------------------------------------------------------
// Launch
// ---------------------------------------------------------------------------
extern "C" void kernel_launch(void* const* d_in, const int* in_sizes, int n_in,
                              void* d_out, int out_size)
{
    const float* x  = (const float*)d_in[0];
    const float* Wq = (const float*)d_in[1];
    const float* bq = (const float*)d_in[2];
    const float* Wk = (const float*)d_in[3];
    const float* bk = (const float*)d_in[4];
    const float* Wv = (const float*)d_in[5];
    const float* bv = (const float*)d_in[6];
    float* out = (float*)d_out;

    __nv_bfloat16 *xh, *xl, *wh, *wl, *Qh, *Ql, *Kh, *Kl;
    __half *Vf, *Pf;
    float* S;
    cudaGetSymbolAddress((void**)&xh, g_xh); cudaGetSymbolAddress((void**)&xl, g_xl);
    cudaGetSymbolAddress((void**)&wh, g_wh); cudaGetSymbolAddress((void**)&wl, g_wl);
    cudaGetSymbolAddress((void**)&Qh, g_Qh); cudaGetSymbolAddress((void**)&Ql, g_Ql);
    cudaGetSymbolAddress((void**)&Kh, g_Kh); cudaGetSymbolAddress((void**)&Kl, g_Kl);
    cudaGetSymbolAddress((void**)&Vf, g_Vf); cudaGetSymbolAddress((void**)&Pf, g_Pf);
    cudaGetSymbolAddress((void**)&S,  g_S);

    const int SMEM3 = 3 * 4 * 10240;    // 122880
    const int SMEMF = 3 * 35840;        // 107520
    cudaFuncSetAttribute(mm3<1, true>,
                         cudaFuncAttributeMaxDynamicSharedMemorySize, SMEM3);
    cudaFuncSetAttribute(mm3<2, true>,
                         cudaFuncAttributeMaxDynamicSharedMemorySize, SMEM3);
    cudaFuncSetAttribute(mm3<0, false>,
                         cudaFuncAttributeMaxDynamicSharedMemorySize, SMEM3);
    cudaFuncSetAttribute(mm_f16,
                         cudaFuncAttributeMaxDynamicSharedMemorySize, SMEMF);

    // 0) pre-split inputs
    {
        const int nx4 = MTOT * DDIM / 4;
        split_kernel<<<(nx4 + 255) / 256, 256>>>(x, xh, xl, nx4);
        const int nw4 = DDIM * DDIM / 4;
        split_kernel<<<(nw4 + 255) / 256, 256>>>(Wq, wh, wl, nw4);
        split_kernel<<<(nw4 + 255) / 256, 256>>>(Wk, wh + DDIM * DDIM,
                                                 wl + DDIM * DDIM, nw4);
        split_kernel<<<(nw4 + 255) / 256, 256>>>(Wv, wh + 2 * DDIM * DDIM,
                                                 wl + 2 * DDIM * DDIM, nw4);
    }
    // 1) projections
    {
        dim3 grid(DDIM / 128, MTOT / 128, 1);
        mm3<1, true><<<grid, 256, SMEM3>>>(
            xh, xl, DDIM, 0, wh, wl, DDIM, 0,
            nullptr, Qh, Ql, nullptr, DDIM, 0, DDIM, bq);
        mm3<1, true><<<grid, 256, SMEM3>>>(
            xh, xl, DDIM, 0, wh + DDIM * DDIM, wl + DDIM * DDIM, DDIM, 0,
            nullptr, Kh, Kl, nullptr, DDIM, 0, DDIM, bk);
        mm3<2, true><<<grid, 256, SMEM3>>>(
            xh, xl, DDIM, 0, wh + 2 * DDIM * DDIM, wl + 2 * DDIM * DDIM, DDIM, 0,
            nullptr, nullptr, nullptr, Vf, DDIM, 0, DDIM, bv);
    }
    // 2) scores: S_b = Q_b @ K_b^T
    {
        dim3 grid(NSQ / 128, NSQ / 128, BB);
        mm3<0, false><<<grid, 256, SMEM3>>>(
            Qh, Ql, DDIM, (long long)NSQ * DDIM,
            Kh, Kl, DDIM, (long long)NSQ * DDIM,
            S, nullptr, nullptr, nullptr, NSQ, (long long)NSQ * NSQ,
            DDIM, nullptr);
    }
    // 3) softmax -> fp16 P
    softmax_f16<<<BB * NSQ, 256>>>(S, Pf);
    // 4) output: O_b = P_b @ V_b  (single-pass fp16)
    {
        dim3 grid(DDIM / 128, NSQ / 128, BB);
        mm_f16<<<grid, 256, SMEMF>>>(
            Pf, NSQ, (long long)NSQ * NSQ,
            Vf, DDIM, (long long)MTOT / BB * DDIM,
            out, DDIM, (long long)NSQ * DDIM, NSQ);
    }
}

// round 13
// speedup vs baseline: 1.3444x; 1.0247x over previous
#include <cuda_runtime.h>
#include <cuda_bf16.h>
#include <cuda_fp16.h>
#include <cstdint>

#define BB   8
#define NSQ  2048
#define DDIM 512
#define MTOT (BB * NSQ)

// ---------------- global scratch ----------------
__device__ __nv_bfloat16 g_xh[(size_t)MTOT * DDIM], g_xl[(size_t)MTOT * DDIM];
__device__ __nv_bfloat16 g_wh[3 * DDIM * DDIM],     g_wl[3 * DDIM * DDIM];
__device__ __nv_bfloat16 g_Qh[(size_t)MTOT * DDIM], g_Ql[(size_t)MTOT * DDIM];
__device__ __nv_bfloat16 g_Kh[(size_t)MTOT * DDIM], g_Kl[(size_t)MTOT * DDIM];
__device__ __half        g_Vf[(size_t)MTOT * DDIM];
__device__ float         g_S [(size_t)BB * NSQ * NSQ];
__device__ __half        g_Pf[(size_t)BB * NSQ * NSQ];

// ---------------------------------------------------------------------------
// helpers
// ---------------------------------------------------------------------------
static __device__ __forceinline__ uint32_t smem_u32(const void* p) {
    uint32_t a;
    asm("{ .reg .u64 t; cvta.to.shared.u64 t, %1; cvt.u32.u64 %0, t; }"
        : "=r"(a) : "l"(p));
    return a;
}
static __device__ __forceinline__ void cpa16(uint32_t dst, const void* src) {
    asm volatile("cp.async.cg.shared.global [%0], [%1], 16;"
                 :: "r"(dst), "l"(src) : "memory");
}
#define CP_COMMIT() asm volatile("cp.async.commit_group;" ::: "memory")
#define CP_WAIT2()  asm volatile("cp.async.wait_group 2;" ::: "memory")
#define CP_WAIT1()  asm volatile("cp.async.wait_group 1;" ::: "memory")
#define CP_WAIT0()  asm volatile("cp.async.wait_group 0;" ::: "memory")

// fp32 x,y -> packed bf16x2 hi (bit-truncate) / lo (rn residual); x low half.
static __device__ __forceinline__ void split2(float x, float y,
                                              uint32_t& hi2, uint32_t& lo2) {
    uint32_t xb = __float_as_uint(x), yb = __float_as_uint(y);
    uint32_t h;
    asm("prmt.b32 %0, %1, %2, 0x7632;" : "=r"(h) : "r"(xb), "r"(yb));
    float xl = x - __uint_as_float(xb & 0xFFFF0000u);
    float yl = y - __uint_as_float(yb & 0xFFFF0000u);
    uint32_t l;
    asm("cvt.rn.bf16x2.f32 %0, %1, %2;" : "=r"(l) : "f"(yl), "f"(xl));
    hi2 = h; lo2 = l;
}
static __device__ __forceinline__ uint32_t packh2(float x, float y) {
    uint32_t r;
    asm("cvt.rn.f16x2.f32 %0, %1, %2;" : "=r"(r) : "f"(y), "f"(x));
    return r;
}

static __device__ __forceinline__ void mma_bf(float c[4], const uint32_t a[4],
                                              uint32_t b0, uint32_t b1) {
    asm volatile(
        "mma.sync.aligned.m16n8k16.row.col.f32.bf16.bf16.f32 "
        "{%0,%1,%2,%3}, {%4,%5,%6,%7}, {%8,%9}, {%0,%1,%2,%3};"
        : "+f"(c[0]), "+f"(c[1]), "+f"(c[2]), "+f"(c[3])
        : "r"(a[0]), "r"(a[1]), "r"(a[2]), "r"(a[3]), "r"(b0), "r"(b1));
}
static __device__ __forceinline__ void mma_fp(float c[4], const uint32_t a[4],
                                              uint32_t b0, uint32_t b1) {
    asm volatile(
        "mma.sync.aligned.m16n8k16.row.col.f32.f16.f16.f32 "
        "{%0,%1,%2,%3}, {%4,%5,%6,%7}, {%8,%9}, {%0,%1,%2,%3};"
        : "+f"(c[0]), "+f"(c[1]), "+f"(c[2]), "+f"(c[3])
        : "r"(a[0]), "r"(a[1]), "r"(a[2]), "r"(a[3]), "r"(b0), "r"(b1));
}

#define LDSM4(r0, r1, r2, r3, addr) \
    asm volatile("ldmatrix.sync.aligned.m8n8.x4.shared.b16 {%0,%1,%2,%3}, [%4];" \
                 : "=r"(r0), "=r"(r1), "=r"(r2), "=r"(r3) : "r"(addr))
#define LDSM4T(r0, r1, r2, r3, addr) \
    asm volatile("ldmatrix.sync.aligned.m8n8.x4.trans.shared.b16 {%0,%1,%2,%3}, [%4];" \
                 : "=r"(r0), "=r"(r1), "=r"(r2), "=r"(r3) : "r"(addr))

// ---------------------------------------------------------------------------
// fp32 -> bf16 hi/lo split
// ---------------------------------------------------------------------------
__global__ __launch_bounds__(256)
void split_kernel(const float* __restrict__ src,
                  __nv_bfloat16* __restrict__ h, __nv_bfloat16* __restrict__ l,
                  int n4)
{
    int i = blockIdx.x * 256 + threadIdx.x;
    if (i >= n4) return;
    float4 v = reinterpret_cast<const float4*>(src)[i];
    uint32_t h0, l0, h1, l1;
    split2(v.x, v.y, h0, l0);
    split2(v.z, v.w, h1, l1);
    reinterpret_cast<uint2*>(h)[i] = make_uint2(h0, h1);
    reinterpret_cast<uint2*>(l)[i] = make_uint2(l0, l1);
}

// ---------------------------------------------------------------------------
// 3xBF16 GEMM core (pre-split operands, both K-major), 4-stage cp.async,
// fragment double-buffered.  MODE 0: QK^T (fp32 C out).
// MODE 1: fused QKV projection (B = stacked [1536,512] weights; epilogue
// routes per 512-column section: Q,K -> bf16 hi/lo, V -> fp16, + bias).
// 256 thr = 8 warps (2m x 4n), warp tile 64x32, BK=32.
// ---------------------------------------------------------------------------
template <int MODE>
__global__ __launch_bounds__(256, 1)
void mm3(const __nv_bfloat16* __restrict__ Ah, const __nv_bfloat16* __restrict__ Al,
         int lda, long long bsA,
         const __nv_bfloat16* __restrict__ Bh, const __nv_bfloat16* __restrict__ Bl,
         int ldb, long long bsB,
         float* __restrict__ C, int ldc, long long bsC, int K,
         __nv_bfloat16* __restrict__ Qh, __nv_bfloat16* __restrict__ Ql,
         __nv_bfloat16* __restrict__ Kh, __nv_bfloat16* __restrict__ Kl,
         __half* __restrict__ Vf,
         const float* __restrict__ bq, const float* __restrict__ bk,
         const float* __restrict__ bv)
{
    constexpr int A_T   = 10240;        // bytes per (hi|lo) tile: 128 x 80B
    constexpr int STAGE = 4 * A_T;      // 40960

    extern __shared__ char smem[];
    const int tid  = threadIdx.x;
    const int lane = tid & 31, w = tid >> 5;
    const int wm = w & 1, wn = w >> 1;
    const int g = lane >> 2, t = lane & 3;
    const int quad = lane >> 3, qi = lane & 7;
    const int m0 = blockIdx.y * 128;
    const int n0 = blockIdx.x * 128;

    const long long aoff = blockIdx.z * bsA + (long long)m0 * lda;
    Ah += aoff; Al += aoff;
    const long long boff = blockIdx.z * bsB + (long long)n0 * ldb;
    Bh += boff; Bl += boff;

    const uint32_t sbase = smem_u32(smem);
    const int KT = K / 32;

    float acc[4][4][4];
#pragma unroll
    for (int mi = 0; mi < 4; mi++)
#pragma unroll
        for (int ni = 0; ni < 4; ni++)
#pragma unroll
            for (int r = 0; r < 4; r++) acc[mi][ni][r] = 0.0f;

    auto load_tile = [&](int stage, int kt) {
        const int kofs = kt * 32;
        const uint32_t st = sbase + stage * STAGE;
#pragma unroll
        for (int j = 0; j < 8; j++) {
            const int idx = tid + j * 256;
            const int arr = idx >> 9;            // 0:Ah 1:Al 2:Bh 3:Bl
            const int rem = idx & 511;
            const int row = rem >> 2, c4 = rem & 3;
            const __nv_bfloat16* gp =
                (arr == 0) ? Ah : (arr == 1) ? Al : (arr == 2) ? Bh : Bl;
            const int ld = (arr < 2) ? lda : ldb;
            cpa16(st + arr * A_T + row * 80 + c4 * 16,
                  gp + (long long)row * ld + kofs + c4 * 8);
        }
    };

    // fragment loads for one 16-wide k-slab
    auto ldfrags = [&](uint32_t st, int kb,
                       uint32_t FAh[4][4], uint32_t FAl[4][4],
                       uint32_t FBh[4][2], uint32_t FBl[4][2]) {
#pragma unroll
        for (int mi = 0; mi < 4; mi++) {
            const uint32_t ro =
                (uint32_t)(wm * 64 + mi * 16 + (quad & 1) * 8 + qi) * 80
                + (uint32_t)(kb + (quad >> 1) * 8) * 2;
            LDSM4(FAh[mi][0], FAh[mi][1], FAh[mi][2], FAh[mi][3], st + ro);
            LDSM4(FAl[mi][0], FAl[mi][1], FAl[mi][2], FAl[mi][3], st + A_T + ro);
        }
#pragma unroll
        for (int nip = 0; nip < 2; nip++) {
            const uint32_t ro =
                (uint32_t)(wn * 32 + nip * 16 + (quad & 1) * 8 + qi) * 80
                + (uint32_t)(kb + (quad >> 1) * 8) * 2;
            uint32_t r0, r1, r2, r3;
            LDSM4(r0, r1, r2, r3, st + 2 * A_T + ro);
            FBh[2 * nip][0] = r0; FBh[2 * nip][1] = r2;
            FBh[2 * nip + 1][0] = r1; FBh[2 * nip + 1][1] = r3;
            LDSM4(r0, r1, r2, r3, st + 3 * A_T + ro);
            FBl[2 * nip][0] = r0; FBl[2 * nip][1] = r2;
            FBl[2 * nip + 1][0] = r1; FBl[2 * nip + 1][1] = r3;
        }
    };
    // term-outermost MMA stream: same-acc ops 16 apart
    auto domma = [&](uint32_t FAh[4][4], uint32_t FAl[4][4],
                     uint32_t FBh[4][2], uint32_t FBl[4][2]) {
#pragma unroll
        for (int mi = 0; mi < 4; mi++)
#pragma unroll
            for (int ni = 0; ni < 4; ni++)
                mma_bf(acc[mi][ni], FAh[mi], FBh[ni][0], FBh[ni][1]);
#pragma unroll
        for (int mi = 0; mi < 4; mi++)
#pragma unroll
            for (int ni = 0; ni < 4; ni++)
                mma_bf(acc[mi][ni], FAh[mi], FBl[ni][0], FBl[ni][1]);
#pragma unroll
        for (int mi = 0; mi < 4; mi++)
#pragma unroll
            for (int ni = 0; ni < 4; ni++)
                mma_bf(acc[mi][ni], FAl[mi], FBh[ni][0], FBh[ni][1]);
    };

    load_tile(0, 0); CP_COMMIT();
    load_tile(1, 1); CP_COMMIT();
    load_tile(2, 2); CP_COMMIT();

    uint32_t FAh[2][4][4], FAl[2][4][4], FBh[2][4][2], FBl[2][4][2];

#pragma unroll 1
    for (int kt = 0; kt < KT; kt++) {
        if (kt < KT - 2)      { CP_WAIT2(); }
        else if (kt == KT - 2){ CP_WAIT1(); }
        else                  { CP_WAIT0(); }
        __syncthreads();
        if (kt + 3 < KT) { load_tile((kt + 3) & 3, kt + 3); CP_COMMIT(); }

        const uint32_t st = sbase + (kt & 3) * STAGE;
        // frag prefetch: issue both k-slab LDSM groups, then MMA streams
        ldfrags(st, 0,  FAh[0], FAl[0], FBh[0], FBl[0]);
        ldfrags(st, 16, FAh[1], FAl[1], FBh[1], FBl[1]);
        domma(FAh[0], FAl[0], FBh[0], FBl[0]);
        domma(FAh[1], FAl[1], FBh[1], FBl[1]);
    }

    // ---- epilogue ---------------------------------------------------------
    if (MODE == 0) {
        const long long coff = blockIdx.z * bsC + (long long)m0 * ldc + n0;
#pragma unroll
        for (int mi = 0; mi < 4; mi++)
#pragma unroll
            for (int ni = 0; ni < 4; ni++) {
                const int col = wn * 32 + ni * 8 + 2 * t;
                const int r0 = wm * 64 + mi * 16 + g;
                *reinterpret_cast<float2*>(C + coff + (long long)r0 * ldc + col) =
                    make_float2(acc[mi][ni][0], acc[mi][ni][1]);
                *reinterpret_cast<float2*>(C + coff + (long long)(r0 + 8) * ldc + col) =
                    make_float2(acc[mi][ni][2], acc[mi][ni][3]);
            }
    } else {
        const int sec = n0 >> 9;                 // 0:Q 1:K 2:V
        const int nbase = n0 & 511;
        const float* bias = (sec == 0) ? bq : (sec == 1) ? bk : bv;
        __nv_bfloat16* OH = (sec == 0) ? Qh : Kh;
        __nv_bfloat16* OL = (sec == 0) ? Ql : Kl;
#pragma unroll
        for (int mi = 0; mi < 4; mi++)
#pragma unroll
            for (int ni = 0; ni < 4; ni++) {
                const int col = nbase + wn * 32 + ni * 8 + 2 * t;
                const float2 bv2 = *reinterpret_cast<const float2*>(bias + col);
                const int r0 = m0 + wm * 64 + mi * 16 + g;
                const float v0 = acc[mi][ni][0] + bv2.x, v1 = acc[mi][ni][1] + bv2.y;
                const float v2 = acc[mi][ni][2] + bv2.x, v3 = acc[mi][ni][3] + bv2.y;
                if (sec < 2) {
                    uint32_t h2, l2;
                    split2(v0, v1, h2, l2);
                    *reinterpret_cast<uint32_t*>(OH + (long long)r0 * DDIM + col) = h2;
                    *reinterpret_cast<uint32_t*>(OL + (long long)r0 * DDIM + col) = l2;
                    split2(v2, v3, h2, l2);
                    *reinterpret_cast<uint32_t*>(OH + (long long)(r0 + 8) * DDIM + col) = h2;
                    *reinterpret_cast<uint32_t*>(OL + (long long)(r0 + 8) * DDIM + col) = l2;
                } else {
                    *reinterpret_cast<uint32_t*>(Vf + (long long)r0 * DDIM + col) =
                        packh2(v0, v1);
                    *reinterpret_cast<uint32_t*>(Vf + (long long)(r0 + 8) * DDIM + col) =
                        packh2(v2, v3);
                }
            }
    }
}

// ---------------------------------------------------------------------------
// Plain fp16 GEMM: C = A[M,K](fp16,K-major) @ B[K,N](fp16,N-major), fp32 out.
// BK=64, 4-stage cp.async, fragment double-buffered.
// ---------------------------------------------------------------------------
__global__ __launch_bounds__(256, 1)
void mm_f16(const __half* __restrict__ A, int lda, long long bsA,
            const __half* __restrict__ B, int ldb, long long bsB,
            float* __restrict__ C, int ldc, long long bsC, int K)
{
    constexpr int A_T   = 128 * 144;    // 18432
    constexpr int B_T   = 64 * 272;     // 17408
    constexpr int STAGE = A_T + B_T;    // 35840

    extern __shared__ char smem[];
    const int tid  = threadIdx.x;
    const int lane = tid & 31, w = tid >> 5;
    const int wm = w & 1, wn = w >> 1;
    const int g = lane >> 2, t = lane & 3;
    const int quad = lane >> 3, qi = lane & 7;
    const int m0 = blockIdx.y * 128;
    const int n0 = blockIdx.x * 128;

    A += blockIdx.z * bsA + (long long)m0 * lda;
    B += blockIdx.z * bsB + n0;
    C += blockIdx.z * bsC + (long long)m0 * ldc + n0;

    const uint32_t sbase = smem_u32(smem);
    const int KT = K / 64;

    float acc[4][4][4];
#pragma unroll
    for (int mi = 0; mi < 4; mi++)
#pragma unroll
        for (int ni = 0; ni < 4; ni++)
#pragma unroll
            for (int r = 0; r < 4; r++) acc[mi][ni][r] = 0.0f;

    auto load_tile = [&](int stage, int kt) {
        const int kofs = kt * 64;
        const uint32_t st = sbase + stage * STAGE;
#pragma unroll
        for (int j = 0; j < 4; j++) {
            const int idx = tid + j * 256;
            const int row = idx >> 3, c4 = idx & 7;
            cpa16(st + row * 144 + c4 * 16,
                  A + (long long)row * lda + kofs + c4 * 8);
        }
#pragma unroll
        for (int j = 0; j < 4; j++) {
            const int idx = tid + j * 256;
            const int row = idx >> 4, c = idx & 15;
            cpa16(st + A_T + row * 272 + c * 16,
                  B + (long long)(kofs + row) * ldb + c * 8);
        }
    };

    auto ldfrags = [&](uint32_t st, int kb, uint32_t FA[4][4], uint32_t FB[4][2]) {
#pragma unroll
        for (int mi = 0; mi < 4; mi++) {
            const uint32_t ro =
                (uint32_t)(wm * 64 + mi * 16 + (quad & 1) * 8 + qi) * 144
                + (uint32_t)(kb + (quad >> 1) * 8) * 2;
            LDSM4(FA[mi][0], FA[mi][1], FA[mi][2], FA[mi][3], st + ro);
        }
#pragma unroll
        for (int nip = 0; nip < 2; nip++) {
            const uint32_t ro =
                (uint32_t)(kb + (quad >> 1) * 8 + qi) * 272
                + (uint32_t)(wn * 32 + nip * 16 + (quad & 1) * 8) * 2;
            uint32_t r0, r1, r2, r3;
            LDSM4T(r0, r1, r2, r3, st + A_T + ro);
            FB[2 * nip][0] = r0; FB[2 * nip][1] = r2;
            FB[2 * nip + 1][0] = r1; FB[2 * nip + 1][1] = r3;
        }
    };

    load_tile(0, 0); CP_COMMIT();
    load_tile(1, 1); CP_COMMIT();
    load_tile(2, 2); CP_COMMIT();

    uint32_t FA[2][4][4], FB[2][4][2];

#pragma unroll 1
    for (int kt = 0; kt < KT; kt++) {
        if (kt < KT - 2)      { CP_WAIT2(); }
        else if (kt == KT - 2){ CP_WAIT1(); }
        else                  { CP_WAIT0(); }
        __syncthreads();
        if (kt + 3 < KT) { load_tile((kt + 3) & 3, kt + 3); CP_COMMIT(); }

        const uint32_t st = sbase + (kt & 3) * STAGE;
        ldfrags(st, 0, FA[0], FB[0]);
#pragma unroll
        for (int ks = 0; ks < 4; ks++) {
            if (ks < 3) ldfrags(st, (ks + 1) * 16, FA[(ks + 1) & 1], FB[(ks + 1) & 1]);
            uint32_t (&fa)[4][4] = FA[ks & 1];
            uint32_t (&fb)[4][2] = FB[ks & 1];
#pragma unroll
            for (int mi = 0; mi < 4; mi++)
#pragma unroll
                for (int ni = 0; ni < 4; ni++)
                    mma_fp(acc[mi][ni], fa[mi], fb[ni][0], fb[ni][1]);
        }
    }

#pragma unroll
    for (int mi = 0; mi < 4; mi++)
#pragma unroll
        for (int ni = 0; ni < 4; ni++) {
            const int col = wn * 32 + ni * 8 + 2 * t;
            const int r0 = wm * 64 + mi * 16 + g;
            *reinterpret_cast<float2*>(C + (long long)r0 * ldc + col) =
                make_float2(acc[mi][ni][0], acc[mi][ni][1]);
            *reinterpret_cast<float2*>(C + (long long)(r0 + 8) * ldc + col) =
                make_float2(acc[mi][ni][2], acc[mi][ni][3]);
        }
}

// ---------------------------------------------------------------------------
// Row softmax (len 2048): fp32 S in, fp16 P out. Shuffle reductions.
// Max-subtraction mandatory (unscaled logits ~±90).
// ---------------------------------------------------------------------------
__global__ __launch_bounds__(256)
void softmax_f16(const float* __restrict__ S, __half* __restrict__ P)
{
    const long long row = blockIdx.x;
    const float* p = S + row * (long long)NSQ;
    const int tid = threadIdx.x;
    const int lane = tid & 31, wid = tid >> 5;

    float v[8];
    {
        float4 a = reinterpret_cast<const float4*>(p)[tid * 2];
        float4 b = reinterpret_cast<const float4*>(p)[tid * 2 + 1];
        v[0] = a.x; v[1] = a.y; v[2] = a.z; v[3] = a.w;
        v[4] = b.x; v[5] = b.y; v[6] = b.z; v[7] = b.w;
    }
    float m = v[0];
#pragma unroll
    for (int i = 1; i < 8; i++) m = fmaxf(m, v[i]);
#pragma unroll
    for (int o = 16; o > 0; o >>= 1)
        m = fmaxf(m, __shfl_xor_sync(0xFFFFFFFFu, m, o));

    __shared__ float red[8];
    if (lane == 0) red[wid] = m;
    __syncthreads();
#pragma unroll
    for (int i = 0; i < 8; i++) m = fmaxf(m, red[i]);
    __syncthreads();

    float sum = 0.0f;
#pragma unroll
    for (int i = 0; i < 8; i++) {
        v[i] = __expf(v[i] - m);
        sum += v[i];
    }
#pragma unroll
    for (int o = 16; o > 0; o >>= 1)
        sum += __shfl_xor_sync(0xFFFFFFFFu, sum, o);
    if (lane == 0) red[wid] = sum;
    __syncthreads();
    sum = 0.0f;
#pragma unroll
    for (int i = 0; i < 8; i++) sum += red[i];
    const float inv = 1.0f / sum;

    uint32_t h[4];
#pragma unroll
    for (int i = 0; i < 4; i++)
        h[i] = packh2(v[2 * i] * inv, v[2 * i + 1] * inv);
    *reinterpret_cast<uint4*>(P + row * (long long)NSQ + tid * 8) =
        make_uint4(h[0], h[1], h[2], h[3]);
}

// ---------------------------------------------------------------------------
// Launch
// ---------------------------------------------------------------------------
extern "C" void kernel_launch(void* const* d_in, const int* in_sizes, int n_in,
                              void* d_out, int out_size)
{
    const float* x  = (const float*)d_in[0];
    const float* Wq = (const float*)d_in[1];
    const float* bq = (const float*)d_in[2];
    const float* Wk = (const float*)d_in[3];
    const float* bk = (const float*)d_in[4];
    const float* Wv = (const float*)d_in[5];
    const float* bv = (const float*)d_in[6];
    float* out = (float*)d_out;

    __nv_bfloat16 *xh, *xl, *wh, *wl, *Qh, *Ql, *Kh, *Kl;
    __half *Vf, *Pf;
    float* S;
    cudaGetSymbolAddress((void**)&xh, g_xh); cudaGetSymbolAddress((void**)&xl, g_xl);
    cudaGetSymbolAddress((void**)&wh, g_wh); cudaGetSymbolAddress((void**)&wl, g_wl);
    cudaGetSymbolAddress((void**)&Qh, g_Qh); cudaGetSymbolAddress((void**)&Ql, g_Ql);
    cudaGetSymbolAddress((void**)&Kh, g_Kh); cudaGetSymbolAddress((void**)&Kl, g_Kl);
    cudaGetSymbolAddress((void**)&Vf, g_Vf); cudaGetSymbolAddress((void**)&Pf, g_Pf);
    cudaGetSymbolAddress((void**)&S,  g_S);

    const int SMEM3 = 4 * 4 * 10240;    // 163840
    const int SMEMF = 4 * 35840;        // 143360
    cudaFuncSetAttribute(mm3<0>,
                         cudaFuncAttributeMaxDynamicSharedMemorySize, SMEM3);
    cudaFuncSetAttribute(mm3<1>,
                         cudaFuncAttributeMaxDynamicSharedMemorySize, SMEM3);
    cudaFuncSetAttribute(mm_f16,
                         cudaFuncAttributeMaxDynamicSharedMemorySize, SMEMF);

    // 0) pre-split inputs
    {
        const int nx4 = MTOT * DDIM / 4;
        split_kernel<<<(nx4 + 255) / 256, 256>>>(x, xh, xl, nx4);
        const int nw4 = DDIM * DDIM / 4;
        split_kernel<<<(nw4 + 255) / 256, 256>>>(Wq, wh, wl, nw4);
        split_kernel<<<(nw4 + 255) / 256, 256>>>(Wk, wh + DDIM * DDIM,
                                                 wl + DDIM * DDIM, nw4);
        split_kernel<<<(nw4 + 255) / 256, 256>>>(Wv, wh + 2 * DDIM * DDIM,
                                                 wl + 2 * DDIM * DDIM, nw4);
    }
    // 1) fused QKV projection: [16384,1536] over stacked weights
    {
        dim3 grid(3 * DDIM / 128, MTOT / 128, 1);
        mm3<1><<<grid, 256, SMEM3>>>(
            xh, xl, DDIM, 0, wh, wl, DDIM, 0,
            nullptr, 0, 0, DDIM,
            Qh, Ql, Kh, Kl, Vf, bq, bk, bv);
    }
    // 2) scores: S_b = Q_b @ K_b^T
    {
        dim3 grid(NSQ / 128, NSQ / 128, BB);
        mm3<0><<<grid, 256, SMEM3>>>(
            Qh, Ql, DDIM, (long long)NSQ * DDIM,
            Kh, Kl, DDIM, (long long)NSQ * DDIM,
            S, NSQ, (long long)NSQ * NSQ, DDIM,
            nullptr, nullptr, nullptr, nullptr, nullptr,
            nullptr, nullptr, nullptr);
    }
    // 3) softmax -> fp16 P
    softmax_f16<<<BB * NSQ, 256>>>(S, Pf);
    // 4) output: O_b = P_b @ V_b
    {
        dim3 grid(DDIM / 128, NSQ / 128, BB);
        mm_f16<<<grid, 256, SMEMF>>>(
            Pf, NSQ, (long long)NSQ * NSQ,
            Vf, DDIM, (long long)NSQ * DDIM,
            out, DDIM, (long long)NSQ * DDIM, NSQ);
    }
}